// round 4
// baseline (speedup 1.0000x reference)
#include <cuda_runtime.h>

#define BB   4
#define SEQ  4096
#define CH   512
#define NH   8
#define HD   64
#define MM   1024          // (64/2)^2 compressed tokens
#define LN_EPS 1e-5f

// ---------------- scratch (device globals; no allocation allowed) ----------------
__device__ float g_q [BB*NH*SEQ*HD];   // [b][h][n][d]
__device__ float g_k [BB*NH*SEQ*HD];
__device__ float g_v [BB*NH*SEQ*HD];
__device__ float g_xr[BB*MM*HD];       // [b][m][d]
__device__ float g_kc[BB*NH*MM*HD];    // [b][h][m][d]
__device__ float g_vc[BB*NH*MM*HD];
__device__ float g_o [BB*SEQ*CH];      // [b][n][c]  pre-proj attention output

// ======================================================================
// GEMM 1: qkv = x @ w_qkv, scatter into g_q/g_k/g_v ([b][h][n][d] layout)
// A: [16384 x 512] row-major, B: [512 x 1536] row-major
// 128x128 tile, k-tile 16, 256 threads, 8x8 micro-tile
// ======================================================================
#define GP 132

__global__ __launch_bounds__(256, 2)
void qkv_gemm_kernel(const float* __restrict__ A, const float* __restrict__ Bw)
{
    __shared__ float As[16*GP];   // As[k*GP + m] (A transposed)
    __shared__ float Bs[16*GP];   // Bs[k*GP + n]
    const int tid = threadIdx.x;
    const int tx = tid & 15, ty = tid >> 4;
    const int m0 = ty * 8, n0 = tx * 8;
    const int bm = blockIdx.y * 128, bn = blockIdx.x * 128;
    const int Kd = 512, ldb = 3 * CH;

    float acc[8][8];
    #pragma unroll
    for (int i = 0; i < 8; i++)
        #pragma unroll
        for (int j = 0; j < 8; j++) acc[i][j] = 0.f;

    for (int k0 = 0; k0 < Kd; k0 += 16) {
        __syncthreads();
        #pragma unroll
        for (int it = 0; it < 2; it++) {
            int s  = tid + it * 256;
            int mr = s >> 2, kq = (s & 3) << 2;
            float4 t = *(const float4*)(A + (long)(bm + mr) * Kd + k0 + kq);
            As[(kq+0)*GP + mr] = t.x;
            As[(kq+1)*GP + mr] = t.y;
            As[(kq+2)*GP + mr] = t.z;
            As[(kq+3)*GP + mr] = t.w;
        }
        #pragma unroll
        for (int it = 0; it < 2; it++) {
            int s  = tid + it * 256;
            int kr = s >> 5, nq = (s & 31) << 2;
            float4 t = *(const float4*)(Bw + (long)(k0 + kr) * ldb + bn + nq);
            *(float4*)(Bs + kr*GP + nq) = t;
        }
        __syncthreads();
        #pragma unroll
        for (int kk = 0; kk < 16; kk++) {
            float a[8], b[8];
            *(float4*)(&a[0]) = *(const float4*)(&As[kk*GP + m0]);
            *(float4*)(&a[4]) = *(const float4*)(&As[kk*GP + m0 + 4]);
            *(float4*)(&b[0]) = *(const float4*)(&Bs[kk*GP + n0]);
            *(float4*)(&b[4]) = *(const float4*)(&Bs[kk*GP + n0 + 4]);
            #pragma unroll
            for (int i = 0; i < 8; i++)
                #pragma unroll
                for (int j = 0; j < 8; j++)
                    acc[i][j] = fmaf(a[i], b[j], acc[i][j]);
        }
    }
    // scatter: col -> (t, h, d); row -> (b, n)
    #pragma unroll
    for (int i = 0; i < 8; i++) {
        int row = bm + m0 + i;
        int b_  = row >> 12, n = row & 4095;
        #pragma unroll
        for (int j = 0; j < 8; j++) {
            int col = bn + n0 + j;
            int t   = col >> 9;
            int rem = col & 511;
            int h   = rem >> 6, d = rem & 63;
            float* dst = (t == 0) ? g_q : ((t == 1) ? g_k : g_v);
            dst[ (((long)(b_ * NH + h) * SEQ) + n) * HD + d ] = acc[i][j];
        }
    }
}

// ======================================================================
// GEMM 2: out = g_o @ w_proj + b_proj   ([16384 x 512] @ [512 x 512])
// ======================================================================
__global__ __launch_bounds__(256, 2)
void proj_gemm_kernel(const float* __restrict__ Bw, const float* __restrict__ bias,
                      float* __restrict__ Out)
{
    __shared__ float As[16*GP];
    __shared__ float Bs[16*GP];
    const int tid = threadIdx.x;
    const int tx = tid & 15, ty = tid >> 4;
    const int m0 = ty * 8, n0 = tx * 8;
    const int bm = blockIdx.y * 128, bn = blockIdx.x * 128;
    const int Kd = 512, ldb = CH;
    const float* A = g_o;

    float acc[8][8];
    #pragma unroll
    for (int i = 0; i < 8; i++)
        #pragma unroll
        for (int j = 0; j < 8; j++) acc[i][j] = 0.f;

    for (int k0 = 0; k0 < Kd; k0 += 16) {
        __syncthreads();
        #pragma unroll
        for (int it = 0; it < 2; it++) {
            int s  = tid + it * 256;
            int mr = s >> 2, kq = (s & 3) << 2;
            float4 t = *(const float4*)(A + (long)(bm + mr) * Kd + k0 + kq);
            As[(kq+0)*GP + mr] = t.x;
            As[(kq+1)*GP + mr] = t.y;
            As[(kq+2)*GP + mr] = t.z;
            As[(kq+3)*GP + mr] = t.w;
        }
        #pragma unroll
        for (int it = 0; it < 2; it++) {
            int s  = tid + it * 256;
            int kr = s >> 5, nq = (s & 31) << 2;
            float4 t = *(const float4*)(Bw + (long)(k0 + kr) * ldb + bn + nq);
            *(float4*)(Bs + kr*GP + nq) = t;
        }
        __syncthreads();
        #pragma unroll
        for (int kk = 0; kk < 16; kk++) {
            float a[8], b[8];
            *(float4*)(&a[0]) = *(const float4*)(&As[kk*GP + m0]);
            *(float4*)(&a[4]) = *(const float4*)(&As[kk*GP + m0 + 4]);
            *(float4*)(&b[0]) = *(const float4*)(&Bs[kk*GP + n0]);
            *(float4*)(&b[4]) = *(const float4*)(&Bs[kk*GP + n0 + 4]);
            #pragma unroll
            for (int i = 0; i < 8; i++)
                #pragma unroll
                for (int j = 0; j < 8; j++)
                    acc[i][j] = fmaf(a[i], b[j], acc[i][j]);
        }
    }
    #pragma unroll
    for (int i = 0; i < 8; i++) {
        long row = bm + m0 + i;
        #pragma unroll
        for (int j = 0; j < 8; j++) {
            int col = bn + n0 + j;
            Out[row * CH + col] = acc[i][j] + bias[col];
        }
    }
}

// ======================================================================
// SR branch: depthwise 2x2/s2 conv + bias -> LayerNorm(C) -> @ w_sr_linear + b
// one block per (b, m); 128 threads
// ======================================================================
__global__ void sr_kernel(const float* __restrict__ x,
                          const float* __restrict__ wconv, const float* __restrict__ bconv,
                          const float* __restrict__ lns,   const float* __restrict__ lnb,
                          const float* __restrict__ wlin,  const float* __restrict__ blin)
{
    __shared__ float y[CH];
    __shared__ float red[2][4];
    const int bm = blockIdx.x;           // b*1024 + m
    const int b_ = bm >> 10, m = bm & 1023;
    const int i = m >> 5, j = m & 31;
    const int tid = threadIdx.x;
    const float* xb = x + (long)b_ * SEQ * CH;
    const int n00 = (2*i) * 64 + 2*j;

    float lsum = 0.f, lsq = 0.f;
    for (int c = tid; c < CH; c += 128) {
        float4 w = *(const float4*)(wconv + c * 4);
        float v = bconv[c];
        v = fmaf(xb[(long)(n00     ) * CH + c], w.x, v);
        v = fmaf(xb[(long)(n00 +  1) * CH + c], w.y, v);
        v = fmaf(xb[(long)(n00 + 64) * CH + c], w.z, v);
        v = fmaf(xb[(long)(n00 + 65) * CH + c], w.w, v);
        y[c] = v;
        lsum += v; lsq += v * v;
    }
    #pragma unroll
    for (int off = 16; off; off >>= 1) {
        lsum += __shfl_xor_sync(0xffffffffu, lsum, off);
        lsq  += __shfl_xor_sync(0xffffffffu, lsq,  off);
    }
    if ((tid & 31) == 0) { red[0][tid >> 5] = lsum; red[1][tid >> 5] = lsq; }
    __syncthreads();
    float tsum = red[0][0] + red[0][1] + red[0][2] + red[0][3];
    float tsq  = red[1][0] + red[1][1] + red[1][2] + red[1][3];
    float mu   = tsum * (1.f / CH);
    float var  = tsq * (1.f / CH) - mu * mu;
    float rstd = rsqrtf(var + LN_EPS);
    for (int c = tid; c < CH; c += 128)
        y[c] = (y[c] - mu) * rstd * lns[c] + lnb[c];
    __syncthreads();
    if (tid < HD) {
        const int d = tid;
        float a = blin[d];
        for (int c = 0; c < CH; c++)
            a = fmaf(y[c], wlin[c * HD + d], a);
        g_xr[(long)bm * HD + d] = a;
    }
}

// ======================================================================
// Generic flash attention: O = softmax(Q K^T * scale) V   (D = 64)
// 64-query tile per block, 64-key chunks, 256 threads (16x16 grid, 4x4 micro)
// batch z: Q at (z/NH)*qb + (z%NH)*qh ; K,V at z*kb ; O at (z/NH)*ob + (z%NH)*oh
// ======================================================================
#define FP 68
#define FLASH_SMEM (4 * 64 * FP * (int)sizeof(float))

__global__ __launch_bounds__(256, 2)
void flash_kernel(const float* __restrict__ Qg, const float* __restrict__ Kg,
                  const float* __restrict__ Vg, float* __restrict__ Og,
                  int nk, float scale, int ostride,
                  long qb, long qh, long kb, long ob, long oh)
{
    extern __shared__ float sm[];
    float* Qs = sm;                 // [d][r]
    float* Ks = sm + 64 * FP;       // [d][j]
    float* Vs = sm + 2 * 64 * FP;   // [j][d]
    float* Ps = sm + 3 * 64 * FP;   // [j][r]

    const int z = blockIdx.z;
    const float* Q = Qg + (long)(z / NH) * qb + (long)(z % NH) * qh;
    const float* K = Kg + (long)z * kb;
    const float* V = Vg + (long)z * kb;
    float*       O = Og + (long)(z / NH) * ob + (long)(z % NH) * oh;

    const int tid = threadIdx.x;
    const int tx = tid & 15, ty = tid >> 4;
    const int r0 = ty * 4, c0 = tx * 4;
    const int qrow0 = blockIdx.x * 64;

    // Q tile -> smem transposed, pre-scaled
    #pragma unroll
    for (int it = 0; it < 4; it++) {
        int s = tid + it * 256;
        int r = s >> 4, dq = (s & 15) << 2;
        float4 t = *(const float4*)(Q + (long)(qrow0 + r) * HD + dq);
        Qs[(dq+0)*FP + r] = t.x * scale;
        Qs[(dq+1)*FP + r] = t.y * scale;
        Qs[(dq+2)*FP + r] = t.z * scale;
        Qs[(dq+3)*FP + r] = t.w * scale;
    }

    float acc[4][4];
    #pragma unroll
    for (int i = 0; i < 4; i++)
        #pragma unroll
        for (int j = 0; j < 4; j++) acc[i][j] = 0.f;
    float mrow[4] = {-1e30f, -1e30f, -1e30f, -1e30f};
    float lrow[4] = {0.f, 0.f, 0.f, 0.f};

    for (int kc = 0; kc < nk; kc += 64) {
        __syncthreads();   // prior chunk's PV reads done
        #pragma unroll
        for (int it = 0; it < 4; it++) {
            int s = tid + it * 256;
            int jj = s >> 4, dq = (s & 15) << 2;
            float4 t = *(const float4*)(K + (long)(kc + jj) * HD + dq);
            Ks[(dq+0)*FP + jj] = t.x;
            Ks[(dq+1)*FP + jj] = t.y;
            Ks[(dq+2)*FP + jj] = t.z;
            Ks[(dq+3)*FP + jj] = t.w;
            float4 u = *(const float4*)(V + (long)(kc + jj) * HD + dq);
            *(float4*)(Vs + jj * FP + dq) = u;
        }
        __syncthreads();

        // S = Q K^T  (64x64x64)
        float s4[4][4];
        #pragma unroll
        for (int i = 0; i < 4; i++)
            #pragma unroll
            for (int j = 0; j < 4; j++) s4[i][j] = 0.f;
        #pragma unroll 4
        for (int d = 0; d < 64; d++) {
            float4 qv = *(const float4*)(Qs + d * FP + r0);
            float4 kv = *(const float4*)(Ks + d * FP + c0);
            float qa[4] = {qv.x, qv.y, qv.z, qv.w};
            float ka[4] = {kv.x, kv.y, kv.z, kv.w};
            #pragma unroll
            for (int i = 0; i < 4; i++)
                #pragma unroll
                for (int j = 0; j < 4; j++)
                    s4[i][j] = fmaf(qa[i], ka[j], s4[i][j]);
        }

        // online softmax per row (reduce across 16 tx lanes)
        float pr[4][4];
        #pragma unroll
        for (int rr = 0; rr < 4; rr++) {
            float mx = fmaxf(fmaxf(s4[rr][0], s4[rr][1]), fmaxf(s4[rr][2], s4[rr][3]));
            #pragma unroll
            for (int off = 8; off; off >>= 1)
                mx = fmaxf(mx, __shfl_xor_sync(0xffffffffu, mx, off));
            float mn = fmaxf(mrow[rr], mx);
            float al = __expf(mrow[rr] - mn);
            mrow[rr] = mn;
            float ps = 0.f;
            #pragma unroll
            for (int cc = 0; cc < 4; cc++) {
                float p = __expf(s4[rr][cc] - mn);
                pr[rr][cc] = p; ps += p;
            }
            #pragma unroll
            for (int off = 8; off; off >>= 1)
                ps += __shfl_xor_sync(0xffffffffu, ps, off);
            lrow[rr] = lrow[rr] * al + ps;
            #pragma unroll
            for (int cc = 0; cc < 4; cc++) acc[rr][cc] *= al;
        }
        // P -> smem transposed [j][r]
        #pragma unroll
        for (int cc = 0; cc < 4; cc++) {
            float4 pv = make_float4(pr[0][cc], pr[1][cc], pr[2][cc], pr[3][cc]);
            *(float4*)(Ps + (c0 + cc) * FP + r0) = pv;
        }
        __syncthreads();

        // O += P V
        #pragma unroll 4
        for (int jj = 0; jj < 64; jj++) {
            float4 pv = *(const float4*)(Ps + jj * FP + r0);
            float4 vv = *(const float4*)(Vs + jj * FP + c0);
            float pa[4] = {pv.x, pv.y, pv.z, pv.w};
            float va[4] = {vv.x, vv.y, vv.z, vv.w};
            #pragma unroll
            for (int i = 0; i < 4; i++)
                #pragma unroll
                for (int j = 0; j < 4; j++)
                    acc[i][j] = fmaf(pa[i], va[j], acc[i][j]);
        }
    }

    #pragma unroll
    for (int rr = 0; rr < 4; rr++) {
        float inv = 1.f / lrow[rr];
        long row = qrow0 + r0 + rr;
        float4 o = make_float4(acc[rr][0] * inv, acc[rr][1] * inv,
                               acc[rr][2] * inv, acc[rr][3] * inv);
        *(float4*)(O + row * (long)ostride + c0) = o;
    }
}

// ======================================================================
extern "C" void kernel_launch(void* const* d_in, const int* in_sizes, int n_in,
                              void* d_out, int out_size)
{
    const float* x        = (const float*)d_in[0];
    const float* w_qkv    = (const float*)d_in[1];
    const float* w_proj   = (const float*)d_in[2];
    const float* b_proj   = (const float*)d_in[3];
    const float* w_sr_c   = (const float*)d_in[4];
    const float* b_sr_c   = (const float*)d_in[5];
    const float* lns      = (const float*)d_in[6];
    const float* lnb      = (const float*)d_in[7];
    const float* w_sr_lin = (const float*)d_in[8];
    const float* b_sr_lin = (const float*)d_in[9];
    float* out = (float*)d_out;

    void *pq, *pk, *pv, *pxr, *pkc, *pvc, *po;
    cudaGetSymbolAddress(&pq,  g_q);
    cudaGetSymbolAddress(&pk,  g_k);
    cudaGetSymbolAddress(&pv,  g_v);
    cudaGetSymbolAddress(&pxr, g_xr);
    cudaGetSymbolAddress(&pkc, g_kc);
    cudaGetSymbolAddress(&pvc, g_vc);
    cudaGetSymbolAddress(&po,  g_o);

    cudaFuncSetAttribute(flash_kernel, cudaFuncAttributeMaxDynamicSharedMemorySize,
                         FLASH_SMEM);

    // 1) QKV projection
    qkv_gemm_kernel<<<dim3(12, 128), 256>>>(x, w_qkv);

    // 2) SR branch -> g_xr [B,M,64]
    sr_kernel<<<BB * MM, 128>>>(x, w_sr_c, b_sr_c, lns, lnb, w_sr_lin, b_sr_lin);

    // 3) K compression: kc = softmax(xr . k) @ k   (scale 1)
    flash_kernel<<<dim3(MM / 64, 1, BB * NH), 256, FLASH_SMEM>>>(
        (const float*)pxr, (const float*)pk, (const float*)pk, (float*)pkc,
        SEQ, 1.0f, HD,
        (long)MM * HD, 0L, (long)SEQ * HD, (long)NH * MM * HD, (long)MM * HD);

    // 4) V compression: vc = softmax(xr . v) @ v
    flash_kernel<<<dim3(MM / 64, 1, BB * NH), 256, FLASH_SMEM>>>(
        (const float*)pxr, (const float*)pv, (const float*)pv, (float*)pvc,
        SEQ, 1.0f, HD,
        (long)MM * HD, 0L, (long)SEQ * HD, (long)NH * MM * HD, (long)MM * HD);

    // 5) main attention: o = softmax(q kc^T / 8) vc  -> g_o [B,N,C]
    flash_kernel<<<dim3(SEQ / 64, 1, BB * NH), 256, FLASH_SMEM>>>(
        (const float*)pq, (const float*)pkc, (const float*)pvc, (float*)po,
        MM, 0.125f, CH,
        (long)NH * SEQ * HD, (long)SEQ * HD, (long)MM * HD, (long)SEQ * CH, (long)HD);

    // 6) output projection
    proj_gemm_kernel<<<dim3(4, 128), 256>>>(w_proj, b_proj, out);
}

// round 6
// speedup vs baseline: 3.5886x; 3.5886x over previous
#include <cuda_runtime.h>

#define BB   4
#define SEQ  4096
#define CH   512
#define NH   8
#define HD   64
#define MM   1024
#define LN_EPS 1e-5f

// ---------------- scratch ----------------
__device__ float g_q [BB*NH*SEQ*HD];
__device__ float g_k [BB*NH*SEQ*HD];
__device__ float g_v [BB*NH*SEQ*HD];
__device__ float g_xr[BB*MM*HD];
__device__ float g_kc[BB*NH*MM*HD];
__device__ float g_vc[BB*NH*MM*HD];
__device__ float g_o [BB*SEQ*CH];

// ---------------- tf32 mma helpers ----------------
__device__ __forceinline__ unsigned f2tf(float f) {
    unsigned u;
    asm("cvt.rna.tf32.f32 %0, %1;" : "=r"(u) : "f"(f));
    return u;
}
__device__ __forceinline__ void mma8(float c[4], unsigned a0, unsigned a1,
                                     unsigned a2, unsigned a3,
                                     unsigned b0, unsigned b1) {
    asm volatile(
        "mma.sync.aligned.m16n8k8.row.col.f32.tf32.tf32.f32 "
        "{%0,%1,%2,%3},{%4,%5,%6,%7},{%8,%9},{%0,%1,%2,%3};"
        : "+f"(c[0]), "+f"(c[1]), "+f"(c[2]), "+f"(c[3])
        : "r"(a0), "r"(a1), "r"(a2), "r"(a3), "r"(b0), "r"(b1));
}
__device__ __forceinline__ unsigned smem_u32(const void* p) {
    return (unsigned)__cvta_generic_to_shared(p);
}
#define CP16(dst_u32, src_ptr) \
    asm volatile("cp.async.cg.shared.global [%0], [%1], 16;" :: "r"(dst_u32), "l"(src_ptr))
#define CP_COMMIT()  asm volatile("cp.async.commit_group;")
#define CP_WAIT1()   asm volatile("cp.async.wait_group 1;")
#define CP_WAIT0()   asm volatile("cp.async.wait_group 0;")

// ======================================================================
// GEMM core: C[128x128] tile of A[.,lda] * B[lda,ldb], tf32 mma
// 256 threads = 8 warps (2x4), warp tile 64x32, k-tile 32 double-buffered
// ======================================================================
#define APAD 36
#define BPAD 136
#define GE_SMEM ((2*128*APAD + 2*32*BPAD) * (int)sizeof(float))

__device__ __forceinline__ void gemm_core_tf32(
    const float* __restrict__ A, int lda,
    const float* __restrict__ Bw, int ldb,
    int bm, int bn, float* sm, int tid, float cfr[4][4][4])
{
    float* As = sm;                 // [2][128][APAD]
    float* Bs = sm + 2*128*APAD;    // [2][32][BPAD]
    const int w = tid >> 5, lane = tid & 31;
    const int g = lane >> 2, t = lane & 3;
    const int wm = (w >> 2) * 64, wn = (w & 3) * 32;

    {   // prefetch k-tile 0 (full tiles: 128x32 A, 32x128 B)
        #pragma unroll
        for (int it = 0; it < 4; it++) {
            int s = tid + it * 256;
            int r = s >> 3, seg = (s & 7) << 2;
            CP16(smem_u32(As + r*APAD + seg), A + (long)(bm + r)*lda + seg);
        }
        #pragma unroll
        for (int it = 0; it < 4; it++) {
            int s = tid + it * 256;
            int rb = s >> 5, segb = (s & 31) << 2;
            CP16(smem_u32(Bs + rb*BPAD + segb), Bw + (long)rb*ldb + bn + segb);
        }
        CP_COMMIT();
    }
    const int NKT = lda / 32;
    for (int kt = 0; kt < NKT; kt++) {
        int buf = kt & 1;
        if (kt + 1 < NKT) {
            int nb = buf ^ 1, k0 = (kt + 1) * 32;
            #pragma unroll
            for (int it = 0; it < 4; it++) {
                int s = tid + it * 256;
                int r = s >> 3, seg = (s & 7) << 2;
                CP16(smem_u32(As + nb*128*APAD + r*APAD + seg),
                     A + (long)(bm + r)*lda + k0 + seg);
            }
            #pragma unroll
            for (int it = 0; it < 4; it++) {
                int s = tid + it * 256;
                int rb = s >> 5, segb = (s & 31) << 2;
                CP16(smem_u32(Bs + nb*32*BPAD + rb*BPAD + segb),
                     Bw + (long)(k0 + rb)*ldb + bn + segb);
            }
            CP_COMMIT();
            CP_WAIT1();
        } else {
            CP_WAIT0();
        }
        __syncthreads();
        const float* Ab = As + buf*128*APAD;
        const float* Bb = Bs + buf*32*BPAD;
        #pragma unroll
        for (int ks = 0; ks < 4; ks++) {
            unsigned af[4][4];
            #pragma unroll
            for (int mt = 0; mt < 4; mt++) {
                const float* ap = Ab + (wm + mt*16 + g)*APAD + ks*8 + t;
                af[mt][0] = f2tf(ap[0]);
                af[mt][1] = f2tf(ap[8*APAD]);
                af[mt][2] = f2tf(ap[4]);
                af[mt][3] = f2tf(ap[8*APAD + 4]);
            }
            unsigned bf[4][2];
            #pragma unroll
            for (int nt = 0; nt < 4; nt++) {
                const float* bp = Bb + (ks*8 + t)*BPAD + wn + nt*8 + g;
                bf[nt][0] = f2tf(bp[0]);
                bf[nt][1] = f2tf(bp[4*BPAD]);
            }
            #pragma unroll
            for (int mt = 0; mt < 4; mt++)
                #pragma unroll
                for (int nt = 0; nt < 4; nt++)
                    mma8(cfr[mt][nt], af[mt][0], af[mt][1], af[mt][2], af[mt][3],
                         bf[nt][0], bf[nt][1]);
        }
        __syncthreads();
    }
}

__global__ __launch_bounds__(256, 2)
void qkv_mma_kernel(const float* __restrict__ A, const float* __restrict__ Bw)
{
    extern __shared__ float sm[];
    float cfr[4][4][4];
    #pragma unroll
    for (int a = 0; a < 4; a++)
        #pragma unroll
        for (int b = 0; b < 4; b++)
            #pragma unroll
            for (int c = 0; c < 4; c++) cfr[a][b][c] = 0.f;

    const int tid = threadIdx.x;
    const int bm = blockIdx.y * 128, bn = blockIdx.x * 128;
    gemm_core_tf32(A, 512, Bw, 3*CH, bm, bn, sm, tid, cfr);

    const int w = tid >> 5, lane = tid & 31;
    const int g = lane >> 2, t = lane & 3;
    const int wm = (w >> 2) * 64, wn = (w & 3) * 32;
    #pragma unroll
    for (int mt = 0; mt < 4; mt++)
        #pragma unroll
        for (int nt = 0; nt < 4; nt++)
            #pragma unroll
            for (int rr = 0; rr < 2; rr++)
                #pragma unroll
                for (int cc = 0; cc < 2; cc++) {
                    int row = bm + wm + mt*16 + g + rr*8;
                    int col = bn + wn + nt*8 + 2*t + cc;
                    int b_ = row >> 12, n = row & 4095;
                    int tc = col >> 9, rem = col & 511;
                    int h = rem >> 6, d = rem & 63;
                    float* dst = (tc == 0) ? g_q : ((tc == 1) ? g_k : g_v);
                    dst[(((long)(b_*NH + h))*SEQ + n)*HD + d] = cfr[mt][nt][rr*2 + cc];
                }
}

__global__ __launch_bounds__(256, 2)
void proj_mma_kernel(const float* __restrict__ Bw, const float* __restrict__ bias,
                     float* __restrict__ Out)
{
    extern __shared__ float sm[];
    float cfr[4][4][4];
    #pragma unroll
    for (int a = 0; a < 4; a++)
        #pragma unroll
        for (int b = 0; b < 4; b++)
            #pragma unroll
            for (int c = 0; c < 4; c++) cfr[a][b][c] = 0.f;

    const int tid = threadIdx.x;
    const int bm = blockIdx.y * 128, bn = blockIdx.x * 128;
    gemm_core_tf32(g_o, 512, Bw, CH, bm, bn, sm, tid, cfr);

    const int w = tid >> 5, lane = tid & 31;
    const int g = lane >> 2, t = lane & 3;
    const int wm = (w >> 2) * 64, wn = (w & 3) * 32;
    #pragma unroll
    for (int mt = 0; mt < 4; mt++)
        #pragma unroll
        for (int nt = 0; nt < 4; nt++)
            #pragma unroll
            for (int rr = 0; rr < 2; rr++) {
                long row = bm + wm + mt*16 + g + rr*8;
                int col = bn + wn + nt*8 + 2*t;
                float2 o = make_float2(cfr[mt][nt][rr*2]     + bias[col],
                                       cfr[mt][nt][rr*2 + 1] + bias[col + 1]);
                *(float2*)(Out + row*CH + col) = o;
            }
}

// ======================================================================
// SR branch (unchanged from passing R3)
// ======================================================================
__global__ void sr_kernel(const float* __restrict__ x,
                          const float* __restrict__ wconv, const float* __restrict__ bconv,
                          const float* __restrict__ lns,   const float* __restrict__ lnb,
                          const float* __restrict__ wlin,  const float* __restrict__ blin)
{
    __shared__ float y[CH];
    __shared__ float red[2][4];
    const int bm = blockIdx.x;
    const int b_ = bm >> 10, m = bm & 1023;
    const int i = m >> 5, j = m & 31;
    const int tid = threadIdx.x;
    const float* xb = x + (long)b_ * SEQ * CH;
    const int n00 = (2*i) * 64 + 2*j;

    float lsum = 0.f, lsq = 0.f;
    for (int c = tid; c < CH; c += 128) {
        float4 w = *(const float4*)(wconv + c * 4);
        float v = bconv[c];
        v = fmaf(xb[(long)(n00     ) * CH + c], w.x, v);
        v = fmaf(xb[(long)(n00 +  1) * CH + c], w.y, v);
        v = fmaf(xb[(long)(n00 + 64) * CH + c], w.z, v);
        v = fmaf(xb[(long)(n00 + 65) * CH + c], w.w, v);
        y[c] = v;
        lsum += v; lsq += v * v;
    }
    #pragma unroll
    for (int off = 16; off; off >>= 1) {
        lsum += __shfl_xor_sync(0xffffffffu, lsum, off);
        lsq  += __shfl_xor_sync(0xffffffffu, lsq,  off);
    }
    if ((tid & 31) == 0) { red[0][tid >> 5] = lsum; red[1][tid >> 5] = lsq; }
    __syncthreads();
    float tsum = red[0][0] + red[0][1] + red[0][2] + red[0][3];
    float tsq  = red[1][0] + red[1][1] + red[1][2] + red[1][3];
    float mu   = tsum * (1.f / CH);
    float var  = tsq * (1.f / CH) - mu * mu;
    float rstd = rsqrtf(var + LN_EPS);
    for (int c = tid; c < CH; c += 128)
        y[c] = (y[c] - mu) * rstd * lns[c] + lnb[c];
    __syncthreads();
    if (tid < HD) {
        const int d = tid;
        float a = blin[d];
        for (int c = 0; c < CH; c++)
            a = fmaf(y[c], wlin[c * HD + d], a);
        g_xr[(long)bm * HD + d] = a;
    }
}

// ======================================================================
// Flash attention with tf32 mma: O = softmax(Q K^T * scale) V   (D=64)
// TQ=128 query tile, TK=64 key chunks, 256 thr = 8 warps (16-row stripes)
// ======================================================================
#define TQ 128
#define TK 64
#define QPAD 68
#define KPAD 68
#define VPAD 72
#define FL_SMEM ((TQ*QPAD + 2*TK*KPAD + 2*TK*VPAD) * (int)sizeof(float))

__global__ __launch_bounds__(256, 1)
void flash_mma_kernel(const float* __restrict__ Qg, const float* __restrict__ Kg,
                      const float* __restrict__ Vg, float* __restrict__ Og,
                      int nk, float scale, int ostride,
                      long qb, long qh, long kb, long ob, long oh)
{
    extern __shared__ float sm[];
    float* Qs = sm;                    // [TQ][QPAD], reused as P (tf32 bits)
    float* Ks = sm + TQ*QPAD;          // [2][TK][KPAD]
    float* Vs = Ks + 2*TK*KPAD;        // [2][TK][VPAD]

    const int z = blockIdx.z;
    const float* Q = Qg + (long)(z / NH) * qb + (long)(z % NH) * qh;
    const float* K = Kg + (long)z * kb;
    const float* V = Vg + (long)z * kb;
    float*       O = Og + (long)(z / NH) * ob + (long)(z % NH) * oh;

    const int tid = threadIdx.x;
    const int w = tid >> 5, lane = tid & 31;
    const int g = lane >> 2, t = lane & 3;
    const int qrow0 = blockIdx.x * TQ;
    const int r_lo = w * 16 + g;

    // G0: stage Q (unscaled) via cp.async  (128 rows x 64 floats)
    #pragma unroll
    for (int it = 0; it < 8; it++) {
        int s = tid + it * 256;
        int r = s >> 4, seg = (s & 15) << 2;
        CP16(smem_u32(Qs + r*QPAD + seg), Q + (long)(qrow0 + r)*HD + seg);
    }
    CP_COMMIT();
    // G1: prefetch K/V chunk 0 (64 rows x 64 floats each)
    #pragma unroll
    for (int it = 0; it < 4; it++) {
        int s = tid + it * 256;
        int j = s >> 4, seg = (s & 15) << 2;
        CP16(smem_u32(Ks + j*KPAD + seg), K + (long)j*HD + seg);
        CP16(smem_u32(Vs + j*VPAD + seg), V + (long)j*HD + seg);
    }
    CP_COMMIT();
    CP_WAIT1();        // Q done (chunk 0 may still be in flight)
    __syncthreads();

    // Q fragments (register-resident, warp-private rows; fold in scale here)
    unsigned qf[8][4];
    #pragma unroll
    for (int kk = 0; kk < 8; kk++) {
        const float* qp = Qs + r_lo * QPAD + kk * 8 + t;
        qf[kk][0] = f2tf(qp[0]            * scale);
        qf[kk][1] = f2tf(qp[8 * QPAD]     * scale);
        qf[kk][2] = f2tf(qp[4]            * scale);
        qf[kk][3] = f2tf(qp[8 * QPAD + 4] * scale);
    }
    __syncthreads();   // everyone done reading Qs before it becomes P

    float oacc[8][4];
    #pragma unroll
    for (int nt = 0; nt < 8; nt++)
        #pragma unroll
        for (int c = 0; c < 4; c++) oacc[nt][c] = 0.f;
    float mrow[2] = {-1e30f, -1e30f};
    float lrow[2] = {0.f, 0.f};

    const int nchunks = nk / TK;
    for (int c = 0; c < nchunks; c++) {
        const int buf = c & 1;
        if (c + 1 < nchunks) {
            int nb = buf ^ 1;
            const float* Kn = K + (long)(c + 1) * TK * HD;
            const float* Vn = V + (long)(c + 1) * TK * HD;
            #pragma unroll
            for (int it = 0; it < 4; it++) {
                int s = tid + it * 256;
                int j = s >> 4, seg = (s & 15) << 2;
                CP16(smem_u32(Ks + nb*TK*KPAD + j*KPAD + seg), Kn + (long)j*HD + seg);
                CP16(smem_u32(Vs + nb*TK*VPAD + j*VPAD + seg), Vn + (long)j*HD + seg);
            }
            CP_COMMIT();
            CP_WAIT1();
        } else {
            CP_WAIT0();
        }
        __syncthreads();
        const float* Kb = Ks + buf*TK*KPAD;
        const float* Vb = Vs + buf*TK*VPAD;

        // S = Q K^T
        float sfr[8][4];
        #pragma unroll
        for (int jt = 0; jt < 8; jt++)
            #pragma unroll
            for (int cc = 0; cc < 4; cc++) sfr[jt][cc] = 0.f;
        #pragma unroll
        for (int kk = 0; kk < 8; kk++) {
            #pragma unroll
            for (int jt = 0; jt < 8; jt++) {
                const float* kp = Kb + (jt*8 + g)*KPAD + kk*8 + t;
                unsigned b0 = f2tf(kp[0]);
                unsigned b1 = f2tf(kp[4]);
                mma8(sfr[jt], qf[kk][0], qf[kk][1], qf[kk][2], qf[kk][3], b0, b1);
            }
        }

        // online softmax (rows r_lo and r_lo+8; reduce across 4-lane groups)
        float mx0 = -1e30f, mx1 = -1e30f;
        #pragma unroll
        for (int jt = 0; jt < 8; jt++) {
            mx0 = fmaxf(mx0, fmaxf(sfr[jt][0], sfr[jt][1]));
            mx1 = fmaxf(mx1, fmaxf(sfr[jt][2], sfr[jt][3]));
        }
        mx0 = fmaxf(mx0, __shfl_xor_sync(0xffffffffu, mx0, 1));
        mx0 = fmaxf(mx0, __shfl_xor_sync(0xffffffffu, mx0, 2));
        mx1 = fmaxf(mx1, __shfl_xor_sync(0xffffffffu, mx1, 1));
        mx1 = fmaxf(mx1, __shfl_xor_sync(0xffffffffu, mx1, 2));
        float mn0 = fmaxf(mrow[0], mx0), mn1 = fmaxf(mrow[1], mx1);
        float al0 = __expf(mrow[0] - mn0), al1 = __expf(mrow[1] - mn1);
        mrow[0] = mn0; mrow[1] = mn1;
        float ps0 = 0.f, ps1 = 0.f;
        #pragma unroll
        for (int jt = 0; jt < 8; jt++) {
            sfr[jt][0] = __expf(sfr[jt][0] - mn0); ps0 += sfr[jt][0];
            sfr[jt][1] = __expf(sfr[jt][1] - mn0); ps0 += sfr[jt][1];
            sfr[jt][2] = __expf(sfr[jt][2] - mn1); ps1 += sfr[jt][2];
            sfr[jt][3] = __expf(sfr[jt][3] - mn1); ps1 += sfr[jt][3];
        }
        ps0 += __shfl_xor_sync(0xffffffffu, ps0, 1);
        ps0 += __shfl_xor_sync(0xffffffffu, ps0, 2);
        ps1 += __shfl_xor_sync(0xffffffffu, ps1, 1);
        ps1 += __shfl_xor_sync(0xffffffffu, ps1, 2);
        lrow[0] = lrow[0] * al0 + ps0;
        lrow[1] = lrow[1] * al1 + ps1;
        #pragma unroll
        for (int nt = 0; nt < 8; nt++) {
            oacc[nt][0] *= al0; oacc[nt][1] *= al0;
            oacc[nt][2] *= al1; oacc[nt][3] *= al1;
        }

        // P -> smem (tf32 bits), warp-private 16-row stripe in dead Q region
        unsigned* Pu = (unsigned*)Qs;
        #pragma unroll
        for (int jt = 0; jt < 8; jt++) {
            *(uint2*)(Pu + r_lo*QPAD + jt*8 + 2*t) =
                make_uint2(f2tf(sfr[jt][0]), f2tf(sfr[jt][1]));
            *(uint2*)(Pu + (r_lo + 8)*QPAD + jt*8 + 2*t) =
                make_uint2(f2tf(sfr[jt][2]), f2tf(sfr[jt][3]));
        }
        __syncwarp();

        // O += P V
        #pragma unroll
        for (int kk = 0; kk < 8; kk++) {
            const unsigned* pp = (const unsigned*)Qs + r_lo*QPAD + kk*8 + t;
            unsigned a0 = pp[0], a1 = pp[8*QPAD], a2 = pp[4], a3 = pp[8*QPAD + 4];
            #pragma unroll
            for (int nt = 0; nt < 8; nt++) {
                const float* vp = Vb + (kk*8 + t)*VPAD + nt*8 + g;
                unsigned b0 = f2tf(vp[0]);
                unsigned b1 = f2tf(vp[4*VPAD]);
                mma8(oacc[nt], a0, a1, a2, a3, b0, b1);
            }
        }
        __syncthreads();   // done with Kb/Vb before next prefetch overwrites
    }

    // epilogue
    #pragma unroll
    for (int rr = 0; rr < 2; rr++) {
        float inv = 1.f / lrow[rr];
        long row = qrow0 + r_lo + rr*8;
        #pragma unroll
        for (int nt = 0; nt < 8; nt++) {
            float2 o = make_float2(oacc[nt][rr*2] * inv, oacc[nt][rr*2 + 1] * inv);
            *(float2*)(O + row * (long)ostride + nt*8 + 2*t) = o;
        }
    }
}

// ======================================================================
extern "C" void kernel_launch(void* const* d_in, const int* in_sizes, int n_in,
                              void* d_out, int out_size)
{
    const float* x        = (const float*)d_in[0];
    const float* w_qkv    = (const float*)d_in[1];
    const float* w_proj   = (const float*)d_in[2];
    const float* b_proj   = (const float*)d_in[3];
    const float* w_sr_c   = (const float*)d_in[4];
    const float* b_sr_c   = (const float*)d_in[5];
    const float* lns      = (const float*)d_in[6];
    const float* lnb      = (const float*)d_in[7];
    const float* w_sr_lin = (const float*)d_in[8];
    const float* b_sr_lin = (const float*)d_in[9];
    float* out = (float*)d_out;

    void *pq, *pk, *pv, *pxr, *pkc, *pvc, *po;
    cudaGetSymbolAddress(&pq,  g_q);
    cudaGetSymbolAddress(&pk,  g_k);
    cudaGetSymbolAddress(&pv,  g_v);
    cudaGetSymbolAddress(&pxr, g_xr);
    cudaGetSymbolAddress(&pkc, g_kc);
    cudaGetSymbolAddress(&pvc, g_vc);
    cudaGetSymbolAddress(&po,  g_o);

    cudaFuncSetAttribute(flash_mma_kernel, cudaFuncAttributeMaxDynamicSharedMemorySize, FL_SMEM);
    cudaFuncSetAttribute(qkv_mma_kernel,  cudaFuncAttributeMaxDynamicSharedMemorySize, GE_SMEM);
    cudaFuncSetAttribute(proj_mma_kernel, cudaFuncAttributeMaxDynamicSharedMemorySize, GE_SMEM);

    // 1) QKV projection (tf32 mma)
    qkv_mma_kernel<<<dim3(12, 128), 256, GE_SMEM>>>(x, w_qkv);

    // 2) SR branch -> g_xr [B,M,64]
    sr_kernel<<<BB * MM, 128>>>(x, w_sr_c, b_sr_c, lns, lnb, w_sr_lin, b_sr_lin);

    // 3) K compression: kc = softmax(xr . k) @ k
    flash_mma_kernel<<<dim3(MM / TQ, 1, BB * NH), 256, FL_SMEM>>>(
        (const float*)pxr, (const float*)pk, (const float*)pk, (float*)pkc,
        SEQ, 1.0f, HD,
        (long)MM * HD, 0L, (long)SEQ * HD, (long)NH * MM * HD, (long)MM * HD);

    // 4) V compression: vc = softmax(xr . v) @ v
    flash_mma_kernel<<<dim3(MM / TQ, 1, BB * NH), 256, FL_SMEM>>>(
        (const float*)pxr, (const float*)pv, (const float*)pv, (float*)pvc,
        SEQ, 1.0f, HD,
        (long)MM * HD, 0L, (long)SEQ * HD, (long)NH * MM * HD, (long)MM * HD);

    // 5) main attention -> g_o [B,N,C]
    flash_mma_kernel<<<dim3(SEQ / TQ, 1, BB * NH), 256, FL_SMEM>>>(
        (const float*)pq, (const float*)pkc, (const float*)pvc, (float*)po,
        MM, 0.125f, CH,
        (long)NH * SEQ * HD, (long)SEQ * HD, (long)MM * HD, (long)SEQ * CH, (long)HD);

    // 6) output projection (tf32 mma)
    proj_mma_kernel<<<dim3(4, 128), 256, GE_SMEM>>>(w_proj, b_proj, out);
}

// round 7
// speedup vs baseline: 4.9265x; 1.3728x over previous
#include <cuda_runtime.h>

#define BB   4
#define SEQ  4096
#define CH   512
#define NH   8
#define HD   64
#define MM   1024
#define LN_EPS 1e-5f
#define LOG2E 1.44269504088896340736f

// ---------------- scratch ----------------
__device__ float g_q [BB*NH*SEQ*HD];
__device__ float g_k [BB*NH*SEQ*HD];
__device__ float g_v [BB*NH*SEQ*HD];
__device__ float g_xr[BB*MM*HD];
__device__ float g_kc[BB*NH*MM*HD];
__device__ float g_vc[BB*NH*MM*HD];
__device__ float g_o [BB*SEQ*CH];

// ---------------- tf32 mma helpers ----------------
__device__ __forceinline__ unsigned f2tf(float f) {
    unsigned u;
    asm("cvt.rna.tf32.f32 %0, %1;" : "=r"(u) : "f"(f));
    return u;
}
__device__ __forceinline__ void mma8(float c[4], unsigned a0, unsigned a1,
                                     unsigned a2, unsigned a3,
                                     unsigned b0, unsigned b1) {
    asm volatile(
        "mma.sync.aligned.m16n8k8.row.col.f32.tf32.tf32.f32 "
        "{%0,%1,%2,%3},{%4,%5,%6,%7},{%8,%9},{%0,%1,%2,%3};"
        : "+f"(c[0]), "+f"(c[1]), "+f"(c[2]), "+f"(c[3])
        : "r"(a0), "r"(a1), "r"(a2), "r"(a3), "r"(b0), "r"(b1));
}
__device__ __forceinline__ unsigned smem_u32(const void* p) {
    return (unsigned)__cvta_generic_to_shared(p);
}
#define CP16(dst_u32, src_ptr) \
    asm volatile("cp.async.cg.shared.global [%0], [%1], 16;" :: "r"(dst_u32), "l"(src_ptr))
#define CP_COMMIT()  asm volatile("cp.async.commit_group;")
#define CP_WAIT1()   asm volatile("cp.async.wait_group 1;")
#define CP_WAIT0()   asm volatile("cp.async.wait_group 0;")

// in-place f32 -> tf32 bits over a float4-aligned smem region
__device__ __forceinline__ void cvt_region_tf32(float* base, int nfloats, int tid) {
    float4* p4 = (float4*)base;
    const int n4 = nfloats >> 2;
    for (int i = tid; i < n4; i += 256) {
        float4 v = p4[i];
        uint4 u = make_uint4(f2tf(v.x), f2tf(v.y), f2tf(v.z), f2tf(v.w));
        *(uint4*)(p4 + i) = u;
    }
}

// ======================================================================
// GEMM core: C[128x128] tile of A[.,lda] * B[lda,ldb], tf32 mma
// 256 threads = 8 warps (2x4), warp tile 64x32, k-tile 32 double-buffered
// ======================================================================
#define APAD 36
#define BPAD 136
#define GE_SMEM ((2*128*APAD + 2*32*BPAD) * (int)sizeof(float))

__device__ __forceinline__ void gemm_core_tf32(
    const float* __restrict__ A, int lda,
    const float* __restrict__ Bw, int ldb,
    int bm, int bn, float* sm, int tid, float cfr[4][4][4])
{
    float* As = sm;                 // [2][128][APAD]
    float* Bs = sm + 2*128*APAD;    // [2][32][BPAD]
    const int w = tid >> 5, lane = tid & 31;
    const int g = lane >> 2, t = lane & 3;
    const int wm = (w >> 2) * 64, wn = (w & 3) * 32;

    {   // prefetch k-tile 0
        #pragma unroll
        for (int it = 0; it < 4; it++) {
            int s = tid + it * 256;
            int r = s >> 3, seg = (s & 7) << 2;
            CP16(smem_u32(As + r*APAD + seg), A + (long)(bm + r)*lda + seg);
        }
        #pragma unroll
        for (int it = 0; it < 4; it++) {
            int s = tid + it * 256;
            int rb = s >> 5, segb = (s & 31) << 2;
            CP16(smem_u32(Bs + rb*BPAD + segb), Bw + (long)rb*ldb + bn + segb);
        }
        CP_COMMIT();
    }
    const int NKT = lda / 32;
    for (int kt = 0; kt < NKT; kt++) {
        int buf = kt & 1;
        if (kt + 1 < NKT) {
            int nb = buf ^ 1, k0 = (kt + 1) * 32;
            #pragma unroll
            for (int it = 0; it < 4; it++) {
                int s = tid + it * 256;
                int r = s >> 3, seg = (s & 7) << 2;
                CP16(smem_u32(As + nb*128*APAD + r*APAD + seg),
                     A + (long)(bm + r)*lda + k0 + seg);
            }
            #pragma unroll
            for (int it = 0; it < 4; it++) {
                int s = tid + it * 256;
                int rb = s >> 5, segb = (s & 31) << 2;
                CP16(smem_u32(Bs + nb*32*BPAD + rb*BPAD + segb),
                     Bw + (long)(k0 + rb)*ldb + bn + segb);
            }
            CP_COMMIT();
            CP_WAIT1();
        } else {
            CP_WAIT0();
        }
        __syncthreads();
        float* Ab = As + buf*128*APAD;
        float* Bb = Bs + buf*32*BPAD;
        // one-shot conversion to tf32 bits
        cvt_region_tf32(Ab, 128*APAD, tid);
        cvt_region_tf32(Bb, 32*BPAD,  tid);
        __syncthreads();
        const unsigned* Au = (const unsigned*)Ab;
        const unsigned* Bu = (const unsigned*)Bb;
        #pragma unroll
        for (int ks = 0; ks < 4; ks++) {
            unsigned af[4][4];
            #pragma unroll
            for (int mt = 0; mt < 4; mt++) {
                const unsigned* ap = Au + (wm + mt*16 + g)*APAD + ks*8 + t;
                af[mt][0] = ap[0];
                af[mt][1] = ap[8*APAD];
                af[mt][2] = ap[4];
                af[mt][3] = ap[8*APAD + 4];
            }
            unsigned bf[4][2];
            #pragma unroll
            for (int nt = 0; nt < 4; nt++) {
                const unsigned* bp = Bu + (ks*8 + t)*BPAD + wn + nt*8 + g;
                bf[nt][0] = bp[0];
                bf[nt][1] = bp[4*BPAD];
            }
            #pragma unroll
            for (int mt = 0; mt < 4; mt++)
                #pragma unroll
                for (int nt = 0; nt < 4; nt++)
                    mma8(cfr[mt][nt], af[mt][0], af[mt][1], af[mt][2], af[mt][3],
                         bf[nt][0], bf[nt][1]);
        }
        __syncthreads();
    }
}

__global__ __launch_bounds__(256, 2)
void qkv_mma_kernel(const float* __restrict__ A, const float* __restrict__ Bw)
{
    extern __shared__ float sm[];
    float cfr[4][4][4];
    #pragma unroll
    for (int a = 0; a < 4; a++)
        #pragma unroll
        for (int b = 0; b < 4; b++)
            #pragma unroll
            for (int c = 0; c < 4; c++) cfr[a][b][c] = 0.f;

    const int tid = threadIdx.x;
    const int bm = blockIdx.y * 128, bn = blockIdx.x * 128;
    gemm_core_tf32(A, 512, Bw, 3*CH, bm, bn, sm, tid, cfr);

    const int w = tid >> 5, lane = tid & 31;
    const int g = lane >> 2, t = lane & 3;
    const int wm = (w >> 2) * 64, wn = (w & 3) * 32;
    #pragma unroll
    for (int mt = 0; mt < 4; mt++)
        #pragma unroll
        for (int nt = 0; nt < 4; nt++)
            #pragma unroll
            for (int rr = 0; rr < 2; rr++)
                #pragma unroll
                for (int cc = 0; cc < 2; cc++) {
                    int row = bm + wm + mt*16 + g + rr*8;
                    int col = bn + wn + nt*8 + 2*t + cc;
                    int b_ = row >> 12, n = row & 4095;
                    int tc = col >> 9, rem = col & 511;
                    int h = rem >> 6, d = rem & 63;
                    float* dst = (tc == 0) ? g_q : ((tc == 1) ? g_k : g_v);
                    dst[(((long)(b_*NH + h))*SEQ + n)*HD + d] = cfr[mt][nt][rr*2 + cc];
                }
}

__global__ __launch_bounds__(256, 2)
void proj_mma_kernel(const float* __restrict__ Bw, const float* __restrict__ bias,
                     float* __restrict__ Out)
{
    extern __shared__ float sm[];
    float cfr[4][4][4];
    #pragma unroll
    for (int a = 0; a < 4; a++)
        #pragma unroll
        for (int b = 0; b < 4; b++)
            #pragma unroll
            for (int c = 0; c < 4; c++) cfr[a][b][c] = 0.f;

    const int tid = threadIdx.x;
    const int bm = blockIdx.y * 128, bn = blockIdx.x * 128;
    gemm_core_tf32(g_o, 512, Bw, CH, bm, bn, sm, tid, cfr);

    const int w = tid >> 5, lane = tid & 31;
    const int g = lane >> 2, t = lane & 3;
    const int wm = (w >> 2) * 64, wn = (w & 3) * 32;
    #pragma unroll
    for (int mt = 0; mt < 4; mt++)
        #pragma unroll
        for (int nt = 0; nt < 4; nt++)
            #pragma unroll
            for (int rr = 0; rr < 2; rr++) {
                long row = bm + wm + mt*16 + g + rr*8;
                int col = bn + wn + nt*8 + 2*t;
                float2 o = make_float2(cfr[mt][nt][rr*2]     + bias[col],
                                       cfr[mt][nt][rr*2 + 1] + bias[col + 1]);
                *(float2*)(Out + row*CH + col) = o;
            }
}

// ======================================================================
// SR branch (unchanged)
// ======================================================================
__global__ void sr_kernel(const float* __restrict__ x,
                          const float* __restrict__ wconv, const float* __restrict__ bconv,
                          const float* __restrict__ lns,   const float* __restrict__ lnb,
                          const float* __restrict__ wlin,  const float* __restrict__ blin)
{
    __shared__ float y[CH];
    __shared__ float red[2][4];
    const int bm = blockIdx.x;
    const int b_ = bm >> 10, m = bm & 1023;
    const int i = m >> 5, j = m & 31;
    const int tid = threadIdx.x;
    const float* xb = x + (long)b_ * SEQ * CH;
    const int n00 = (2*i) * 64 + 2*j;

    float lsum = 0.f, lsq = 0.f;
    for (int c = tid; c < CH; c += 128) {
        float4 w = *(const float4*)(wconv + c * 4);
        float v = bconv[c];
        v = fmaf(xb[(long)(n00     ) * CH + c], w.x, v);
        v = fmaf(xb[(long)(n00 +  1) * CH + c], w.y, v);
        v = fmaf(xb[(long)(n00 + 64) * CH + c], w.z, v);
        v = fmaf(xb[(long)(n00 + 65) * CH + c], w.w, v);
        y[c] = v;
        lsum += v; lsq += v * v;
    }
    #pragma unroll
    for (int off = 16; off; off >>= 1) {
        lsum += __shfl_xor_sync(0xffffffffu, lsum, off);
        lsq  += __shfl_xor_sync(0xffffffffu, lsq,  off);
    }
    if ((tid & 31) == 0) { red[0][tid >> 5] = lsum; red[1][tid >> 5] = lsq; }
    __syncthreads();
    float tsum = red[0][0] + red[0][1] + red[0][2] + red[0][3];
    float tsq  = red[1][0] + red[1][1] + red[1][2] + red[1][3];
    float mu   = tsum * (1.f / CH);
    float var  = tsq * (1.f / CH) - mu * mu;
    float rstd = rsqrtf(var + LN_EPS);
    for (int c = tid; c < CH; c += 128)
        y[c] = (y[c] - mu) * rstd * lns[c] + lnb[c];
    __syncthreads();
    if (tid < HD) {
        const int d = tid;
        float a = blin[d];
        for (int c = 0; c < CH; c++)
            a = fmaf(y[c], wlin[c * HD + d], a);
        g_xr[(long)bm * HD + d] = a;
    }
}

// ======================================================================
// Flash attention body (tf32 mma, log2-domain softmax)
// TQ=128 query tile, TK=64 key chunks, 256 thr = 8 warps (16-row stripes)
// qscale must include LOG2E.
// ======================================================================
#define TQ 128
#define TK 64
#define QPAD 68
#define KPAD 68
#define VPAD 72
#define FL_SMEM ((TQ*QPAD + 2*TK*KPAD + 2*TK*VPAD) * (int)sizeof(float))

__device__ __forceinline__ void flash_body(
    const float* __restrict__ Q, const float* __restrict__ K,
    const float* __restrict__ V, float* __restrict__ O,
    int nk, float qscale, int ostride)
{
    extern __shared__ float sm[];
    float* Qs = sm;                    // [TQ][QPAD], reused as P (tf32 bits)
    float* Ks = sm + TQ*QPAD;          // [2][TK][KPAD]
    float* Vs = Ks + 2*TK*KPAD;        // [2][TK][VPAD]

    const int tid = threadIdx.x;
    const int w = tid >> 5, lane = tid & 31;
    const int g = lane >> 2, t = lane & 3;
    const int qrow0 = blockIdx.x * TQ;
    const int r_lo = w * 16 + g;

    // G0: stage Q (unscaled)
    #pragma unroll
    for (int it = 0; it < 8; it++) {
        int s = tid + it * 256;
        int r = s >> 4, seg = (s & 15) << 2;
        CP16(smem_u32(Qs + r*QPAD + seg), Q + (long)(qrow0 + r)*HD + seg);
    }
    CP_COMMIT();
    // G1: prefetch K/V chunk 0
    #pragma unroll
    for (int it = 0; it < 4; it++) {
        int s = tid + it * 256;
        int j = s >> 4, seg = (s & 15) << 2;
        CP16(smem_u32(Ks + j*KPAD + seg), K + (long)j*HD + seg);
        CP16(smem_u32(Vs + j*VPAD + seg), V + (long)j*HD + seg);
    }
    CP_COMMIT();
    CP_WAIT1();
    __syncthreads();

    // Q fragments (scale * LOG2E folded in)
    unsigned qf[8][4];
    #pragma unroll
    for (int kk = 0; kk < 8; kk++) {
        const float* qp = Qs + r_lo * QPAD + kk * 8 + t;
        qf[kk][0] = f2tf(qp[0]            * qscale);
        qf[kk][1] = f2tf(qp[8 * QPAD]     * qscale);
        qf[kk][2] = f2tf(qp[4]            * qscale);
        qf[kk][3] = f2tf(qp[8 * QPAD + 4] * qscale);
    }
    __syncthreads();   // Qs becomes P region

    float oacc[8][4];
    #pragma unroll
    for (int nt = 0; nt < 8; nt++)
        #pragma unroll
        for (int c = 0; c < 4; c++) oacc[nt][c] = 0.f;
    float mrow[2] = {-1e30f, -1e30f};
    float lrow[2] = {0.f, 0.f};

    const int nchunks = nk / TK;
    for (int c = 0; c < nchunks; c++) {
        const int buf = c & 1;
        if (c + 1 < nchunks) {
            int nb = buf ^ 1;
            const float* Kn = K + (long)(c + 1) * TK * HD;
            const float* Vn = V + (long)(c + 1) * TK * HD;
            #pragma unroll
            for (int it = 0; it < 4; it++) {
                int s = tid + it * 256;
                int j = s >> 4, seg = (s & 15) << 2;
                CP16(smem_u32(Ks + nb*TK*KPAD + j*KPAD + seg), Kn + (long)j*HD + seg);
                CP16(smem_u32(Vs + nb*TK*VPAD + j*VPAD + seg), Vn + (long)j*HD + seg);
            }
            CP_COMMIT();
            CP_WAIT1();
        } else {
            CP_WAIT0();
        }
        __syncthreads();
        float* Kb = Ks + buf*TK*KPAD;
        float* Vb = Vs + buf*TK*VPAD;
        // one-shot tf32 conversion of the whole K/V chunk
        cvt_region_tf32(Kb, TK*KPAD, tid);
        cvt_region_tf32(Vb, TK*VPAD, tid);
        __syncthreads();
        const unsigned* Ku = (const unsigned*)Kb;
        const unsigned* Vu = (const unsigned*)Vb;

        // S = Q K^T
        float sfr[8][4];
        #pragma unroll
        for (int jt = 0; jt < 8; jt++)
            #pragma unroll
            for (int cc = 0; cc < 4; cc++) sfr[jt][cc] = 0.f;
        #pragma unroll
        for (int kk = 0; kk < 8; kk++) {
            #pragma unroll
            for (int jt = 0; jt < 8; jt++) {
                const unsigned* kp = Ku + (jt*8 + g)*KPAD + kk*8 + t;
                mma8(sfr[jt], qf[kk][0], qf[kk][1], qf[kk][2], qf[kk][3],
                     kp[0], kp[4]);
            }
        }

        // online softmax (log2 domain)
        float mx0 = -1e30f, mx1 = -1e30f;
        #pragma unroll
        for (int jt = 0; jt < 8; jt++) {
            mx0 = fmaxf(mx0, fmaxf(sfr[jt][0], sfr[jt][1]));
            mx1 = fmaxf(mx1, fmaxf(sfr[jt][2], sfr[jt][3]));
        }
        mx0 = fmaxf(mx0, __shfl_xor_sync(0xffffffffu, mx0, 1));
        mx0 = fmaxf(mx0, __shfl_xor_sync(0xffffffffu, mx0, 2));
        mx1 = fmaxf(mx1, __shfl_xor_sync(0xffffffffu, mx1, 1));
        mx1 = fmaxf(mx1, __shfl_xor_sync(0xffffffffu, mx1, 2));
        float mn0 = fmaxf(mrow[0], mx0), mn1 = fmaxf(mrow[1], mx1);
        float al0 = exp2f(mrow[0] - mn0), al1 = exp2f(mrow[1] - mn1);
        mrow[0] = mn0; mrow[1] = mn1;
        float ps0 = 0.f, ps1 = 0.f;
        #pragma unroll
        for (int jt = 0; jt < 8; jt++) {
            sfr[jt][0] = exp2f(sfr[jt][0] - mn0); ps0 += sfr[jt][0];
            sfr[jt][1] = exp2f(sfr[jt][1] - mn0); ps0 += sfr[jt][1];
            sfr[jt][2] = exp2f(sfr[jt][2] - mn1); ps1 += sfr[jt][2];
            sfr[jt][3] = exp2f(sfr[jt][3] - mn1); ps1 += sfr[jt][3];
        }
        ps0 += __shfl_xor_sync(0xffffffffu, ps0, 1);
        ps0 += __shfl_xor_sync(0xffffffffu, ps0, 2);
        ps1 += __shfl_xor_sync(0xffffffffu, ps1, 1);
        ps1 += __shfl_xor_sync(0xffffffffu, ps1, 2);
        lrow[0] = lrow[0] * al0 + ps0;
        lrow[1] = lrow[1] * al1 + ps1;
        #pragma unroll
        for (int nt = 0; nt < 8; nt++) {
            oacc[nt][0] *= al0; oacc[nt][1] *= al0;
            oacc[nt][2] *= al1; oacc[nt][3] *= al1;
        }

        // P -> smem (tf32 bits), warp-private 16-row stripe in dead Q region
        unsigned* Pu = (unsigned*)Qs;
        #pragma unroll
        for (int jt = 0; jt < 8; jt++) {
            *(uint2*)(Pu + r_lo*QPAD + jt*8 + 2*t) =
                make_uint2(f2tf(sfr[jt][0]), f2tf(sfr[jt][1]));
            *(uint2*)(Pu + (r_lo + 8)*QPAD + jt*8 + 2*t) =
                make_uint2(f2tf(sfr[jt][2]), f2tf(sfr[jt][3]));
        }
        __syncwarp();

        // O += P V
        #pragma unroll
        for (int kk = 0; kk < 8; kk++) {
            const unsigned* pp = (const unsigned*)Qs + r_lo*QPAD + kk*8 + t;
            unsigned a0 = pp[0], a1 = pp[8*QPAD], a2 = pp[4], a3 = pp[8*QPAD + 4];
            #pragma unroll
            for (int nt = 0; nt < 8; nt++) {
                const unsigned* vp = Vu + (kk*8 + t)*VPAD + nt*8 + g;
                mma8(oacc[nt], a0, a1, a2, a3, vp[0], vp[4*VPAD]);
            }
        }
        __syncthreads();   // done with Kb/Vb before next prefetch overwrites
    }

    // epilogue
    #pragma unroll
    for (int rr = 0; rr < 2; rr++) {
        float inv = 1.f / lrow[rr];
        long row = qrow0 + r_lo + rr*8;
        #pragma unroll
        for (int nt = 0; nt < 8; nt++) {
            float2 o = make_float2(oacc[nt][rr*2] * inv, oacc[nt][rr*2 + 1] * inv);
            *(float2*)(O + row * (long)ostride + nt*8 + 2*t) = o;
        }
    }
}

// fused K+V compression: z in [0,64): z<32 -> K branch, else V branch
__global__ __launch_bounds__(256, 1)
void compress_kernel()
{
    const int z = blockIdx.z;
    const int zz = z & 31;                  // b*NH + h
    const float* T = (z < 32) ? g_k : g_v;
    float* Oc      = (z < 32) ? g_kc : g_vc;
    const float* Q = g_xr + (long)(zz / NH) * MM * HD;
    const float* KV = T + (long)zz * SEQ * HD;
    float* O = Oc + (long)zz * MM * HD;
    flash_body(Q, KV, KV, O, SEQ, LOG2E, HD);
}

// main attention: z in [0,32)
__global__ __launch_bounds__(256, 1)
void attn_kernel()
{
    const int z = blockIdx.z;
    const float* Q = g_q  + (long)z * SEQ * HD;
    const float* K = g_kc + (long)z * MM * HD;
    const float* V = g_vc + (long)z * MM * HD;
    float* O = g_o + (long)(z / NH) * SEQ * CH + (long)(z % NH) * HD;
    flash_body(Q, K, V, O, MM, 0.125f * LOG2E, CH);
}

// ======================================================================
extern "C" void kernel_launch(void* const* d_in, const int* in_sizes, int n_in,
                              void* d_out, int out_size)
{
    const float* x        = (const float*)d_in[0];
    const float* w_qkv    = (const float*)d_in[1];
    const float* w_proj   = (const float*)d_in[2];
    const float* b_proj   = (const float*)d_in[3];
    const float* w_sr_c   = (const float*)d_in[4];
    const float* b_sr_c   = (const float*)d_in[5];
    const float* lns      = (const float*)d_in[6];
    const float* lnb      = (const float*)d_in[7];
    const float* w_sr_lin = (const float*)d_in[8];
    const float* b_sr_lin = (const float*)d_in[9];
    float* out = (float*)d_out;

    cudaFuncSetAttribute(compress_kernel, cudaFuncAttributeMaxDynamicSharedMemorySize, FL_SMEM);
    cudaFuncSetAttribute(attn_kernel,     cudaFuncAttributeMaxDynamicSharedMemorySize, FL_SMEM);
    cudaFuncSetAttribute(qkv_mma_kernel,  cudaFuncAttributeMaxDynamicSharedMemorySize, GE_SMEM);
    cudaFuncSetAttribute(proj_mma_kernel, cudaFuncAttributeMaxDynamicSharedMemorySize, GE_SMEM);

    // 1) QKV projection
    qkv_mma_kernel<<<dim3(12, 128), 256, GE_SMEM>>>(x, w_qkv);

    // 2) SR branch -> g_xr
    sr_kernel<<<BB * MM, 128>>>(x, w_sr_c, b_sr_c, lns, lnb, w_sr_lin, b_sr_lin);

    // 3+4) fused K/V compression
    compress_kernel<<<dim3(MM / TQ, 1, 2 * BB * NH), 256, FL_SMEM>>>();

    // 5) main attention -> g_o
    attn_kernel<<<dim3(SEQ / TQ, 1, BB * NH), 256, FL_SMEM>>>();

    // 6) output projection
    proj_mma_kernel<<<dim3(4, 128), 256, GE_SMEM>>>(w_proj, b_proj, out);
}